// round 1
// baseline (speedup 1.0000x reference)
#include <cuda_runtime.h>
#include <math.h>

// Problem dims
#define LL  4
#define BB  2
#define SSq 512
#define MMm 512
#define DDd 1024
#define HHh 16
#define DKk 64
#define FFf 4096
#define TTt (SSq + MMm)   // 1024

// ---------------- scratch (device globals; no allocation allowed) ----------------
__device__ float g_pos[TTt * DDd];                    // [T, D] sinusoidal encodings
__device__ float g_kv [BB * TTt * DDd];               // concat(memory, h)
__device__ float g_q  [BB * SSq * DDd];               // scaled q
__device__ float g_k  [BB * TTt * DDd];
__device__ float g_v  [BB * TTt * DDd];
__device__ float g_r  [TTt * DDd];
__device__ float g_sc [(size_t)BB * HHh * SSq * TTt]; // content logits -> softmax weights
__device__ float g_rel[(size_t)BB * HHh * SSq * TTt]; // unshifted relative logits
__device__ float g_attn[BB * SSq * DDd];
__device__ float g_tmp [BB * SSq * DDd];
__device__ float g_ff  [BB * SSq * FFf];
__device__ float g_h   [BB * SSq * DDd];
__device__ float g_h1  [BB * SSq * DDd];

// ---------------- positional encodings ----------------
__global__ void pos_kernel(float* __restrict__ pos)
{
    int idx = blockIdx.x * blockDim.x + threadIdx.x;
    if (idx >= TTt * DDd) return;
    int t = idx / DDd, d = idx % DDd;
    int j = (d < DDd / 2) ? d : d - DDd / 2;
    double invf = exp(-((double)(2 * j) / (double)DDd) * log(10000.0));
    double ang  = (double)(TTt - 1 - t) * invf;
    pos[idx] = (d < DDd / 2) ? (float)sin(ang) : (float)cos(ang);
}

// ---------------- concat(memory[l], h) -> kv ----------------
__global__ void concat_kernel(float* __restrict__ kv, const float* __restrict__ mem,
                              const float* __restrict__ h)
{
    int idx = blockIdx.x * blockDim.x + threadIdx.x;
    if (idx >= BB * TTt * DDd) return;
    int d = idx % DDd;
    int t = (idx / DDd) % TTt;
    int b = idx / (DDd * TTt);
    kv[idx] = (t < MMm) ? mem[((size_t)b * MMm + t) * DDd + d]
                        : h[((size_t)b * SSq + (t - MMm)) * DDd + d];
}

// ---------------- generic SGEMM: C[M,N] = alpha*A[M,K]@B[K,N] (+bias)(+relu) ----------
// BM=128, BN=64, BK=8; 256 threads; 8x4 per thread. Requires M%128==0, N%64==0, K%8==0.
__global__ void sgemm_kernel(const float* __restrict__ A, const float* __restrict__ B,
                             float* __restrict__ C, int M, int N, int K, float alpha,
                             const float* __restrict__ bias, int relu)
{
    __shared__ float As[8][128];
    __shared__ float Bs[8][64];
    int tid = threadIdx.x;
    const float* Ag = A + (size_t)blockIdx.y * 128 * K;
    const float* Bg = B + blockIdx.x * 64;

    int arow = tid >> 1;           // 0..127
    int acol = (tid & 1) * 4;      // 0 or 4
    int brow = tid >> 5;           // 0..7
    int bcol = (tid & 31) * 2;     // 0..62
    int tx = tid & 15, ty = tid >> 4;

    float acc[8][4];
#pragma unroll
    for (int i = 0; i < 8; i++)
#pragma unroll
        for (int j = 0; j < 4; j++) acc[i][j] = 0.f;

    for (int k0 = 0; k0 < K; k0 += 8) {
        float4 av = *(const float4*)(Ag + (size_t)arow * K + k0 + acol);
        As[acol + 0][arow] = av.x;
        As[acol + 1][arow] = av.y;
        As[acol + 2][arow] = av.z;
        As[acol + 3][arow] = av.w;
        float2 bv = *(const float2*)(Bg + (size_t)(k0 + brow) * N + bcol);
        Bs[brow][bcol] = bv.x;
        Bs[brow][bcol + 1] = bv.y;
        __syncthreads();
#pragma unroll
        for (int k = 0; k < 8; k++) {
            float a[8], bb[4];
#pragma unroll
            for (int i = 0; i < 8; i++) a[i] = As[k][ty * 8 + i];
#pragma unroll
            for (int j = 0; j < 4; j++) bb[j] = Bs[k][tx * 4 + j];
#pragma unroll
            for (int i = 0; i < 8; i++)
#pragma unroll
                for (int j = 0; j < 4; j++) acc[i][j] += a[i] * bb[j];
        }
        __syncthreads();
    }

#pragma unroll
    for (int i = 0; i < 8; i++) {
        int m = blockIdx.y * 128 + ty * 8 + i;
#pragma unroll
        for (int j = 0; j < 4; j++) {
            int n = blockIdx.x * 64 + tx * 4 + j;
            float vv = acc[i][j] * alpha;
            if (bias) vv += bias[n];
            if (relu) vv = fmaxf(vv, 0.f);
            C[(size_t)m * N + n] = vv;
        }
    }
}

// ---------------- batched scores: out[b,h,s,t] = sum_dk (Q[b,s,h,dk]+bias[h,dk]) * KR[(b,)t,h,dk]
__global__ void scores_kernel(const float* __restrict__ Q, const float* __restrict__ qbias,
                              const float* __restrict__ KR, int batched,
                              float* __restrict__ out)
{
    // grid: (T/64, S/64, B*H)
    int b = blockIdx.z / HHh, h = blockIdx.z % HHh;
    const float* qb = Q + (size_t)b * SSq * DDd + h * DKk;
    const float* kb = KR + (batched ? (size_t)b * TTt * DDd : 0) + h * DKk;
    const float* bias = qbias + h * DKk;

    __shared__ float Asm[DKk][65];  // [dk][s]
    __shared__ float Bsm[DKk][65];  // [dk][t]
    int tid = threadIdx.x;
    int s0 = blockIdx.y * 64, t0 = blockIdx.x * 64;

    for (int e = tid; e < 64 * 64; e += 256) {
        int row = e >> 6, dk = e & 63;
        Asm[dk][row] = qb[(size_t)(s0 + row) * DDd + dk] + bias[dk];
        Bsm[dk][row] = kb[(size_t)(t0 + row) * DDd + dk];
    }
    __syncthreads();

    int tx = tid & 15, ty = tid >> 4;
    float acc[4][4];
#pragma unroll
    for (int i = 0; i < 4; i++)
#pragma unroll
        for (int j = 0; j < 4; j++) acc[i][j] = 0.f;

#pragma unroll 8
    for (int k = 0; k < 64; k++) {
        float a[4], bv[4];
#pragma unroll
        for (int i = 0; i < 4; i++) a[i] = Asm[k][ty * 4 + i];
#pragma unroll
        for (int j = 0; j < 4; j++) bv[j] = Bsm[k][tx * 4 + j];
#pragma unroll
        for (int i = 0; i < 4; i++)
#pragma unroll
            for (int j = 0; j < 4; j++) acc[i][j] += a[i] * bv[j];
    }

#pragma unroll
    for (int i = 0; i < 4; i++)
#pragma unroll
        for (int j = 0; j < 4; j++) {
            size_t o = ((size_t)blockIdx.z * SSq + s0 + ty * 4 + i) * TTt + t0 + tx * 4 + j;
            out[o] = acc[i][j];
        }
}

// ---------------- shift + mask + softmax (in-place on sc) ----------------
// logits[s,t] = sc[s,t] + rel[s, t-s+S-1] for t <= M+s; else fully masked (exact 0 weight)
__global__ void softmax_kernel(float* __restrict__ sc, const float* __restrict__ rel)
{
    int row = blockIdx.x;          // over B*H*S
    int s = row % SSq;
    float* lr = sc + (size_t)row * TTt;
    const float* rr = rel + (size_t)row * TTt;
    int valid = MMm + s + 1;

    __shared__ float vals[TTt];
    __shared__ float red[33];
    int tid = threadIdx.x;

    float lmax = -1e30f;
    for (int t = tid; t < TTt; t += 256) {
        float v = -1e30f;
        if (t < valid) v = lr[t] + rr[t - s + SSq - 1];
        vals[t] = v;
        lmax = fmaxf(lmax, v);
    }
#pragma unroll
    for (int o = 16; o; o >>= 1) lmax = fmaxf(lmax, __shfl_xor_sync(0xffffffffu, lmax, o));
    if ((tid & 31) == 0) red[tid >> 5] = lmax;
    __syncthreads();
    if (tid < 32) {
        float v2 = (tid < 8) ? red[tid] : -1e30f;
#pragma unroll
        for (int o = 4; o; o >>= 1) v2 = fmaxf(v2, __shfl_xor_sync(0xffffffffu, v2, o));
        if (tid == 0) red[32] = v2;
    }
    __syncthreads();
    float m = red[32];
    __syncthreads();

    float lsum = 0.f;
    for (int t = tid; t < TTt; t += 256) {
        float e = (t < valid) ? __expf(vals[t] - m) : 0.f;
        vals[t] = e;
        lsum += e;
    }
#pragma unroll
    for (int o = 16; o; o >>= 1) lsum += __shfl_xor_sync(0xffffffffu, lsum, o);
    if ((tid & 31) == 0) red[tid >> 5] = lsum;
    __syncthreads();
    if (tid < 32) {
        float v2 = (tid < 8) ? red[tid] : 0.f;
#pragma unroll
        for (int o = 4; o; o >>= 1) v2 += __shfl_xor_sync(0xffffffffu, v2, o);
        if (tid == 0) red[32] = v2;
    }
    __syncthreads();
    float inv = 1.f / red[32];
    for (int t = tid; t < TTt; t += 256) lr[t] = vals[t] * inv;
}

// ---------------- attn[b,s,h,dk] = sum_t W[b,h,s,t] * V[b,t,h,dk] ----------------
__global__ void attnv_kernel(const float* __restrict__ W, const float* __restrict__ V,
                             float* __restrict__ out)
{
    // grid: (S/64, B*H)
    int b = blockIdx.y / HHh, h = blockIdx.y % HHh;
    const float* wb = W + (size_t)blockIdx.y * SSq * TTt;
    const float* vb = V + (size_t)b * TTt * DDd + h * DKk;

    __shared__ float Ws[64][65];   // [s][t]
    __shared__ float Vs[64][65];   // [t][dk]
    int tid = threadIdx.x;
    int s0 = blockIdx.x * 64;
    int tx = tid & 15, ty = tid >> 4;

    float acc[4][4];
#pragma unroll
    for (int i = 0; i < 4; i++)
#pragma unroll
        for (int j = 0; j < 4; j++) acc[i][j] = 0.f;

    for (int k0 = 0; k0 < TTt; k0 += 64) {
        for (int e = tid; e < 64 * 64; e += 256) {
            int row = e >> 6, col = e & 63;
            Ws[row][col] = wb[(size_t)(s0 + row) * TTt + k0 + col];
            Vs[row][col] = vb[(size_t)(k0 + row) * DDd + col];
        }
        __syncthreads();
#pragma unroll 8
        for (int k = 0; k < 64; k++) {
            float a[4], bv[4];
#pragma unroll
            for (int i = 0; i < 4; i++) a[i] = Ws[ty * 4 + i][k];
#pragma unroll
            for (int j = 0; j < 4; j++) bv[j] = Vs[k][tx * 4 + j];
#pragma unroll
            for (int i = 0; i < 4; i++)
#pragma unroll
                for (int j = 0; j < 4; j++) acc[i][j] += a[i] * bv[j];
        }
        __syncthreads();
    }

#pragma unroll
    for (int i = 0; i < 4; i++)
#pragma unroll
        for (int j = 0; j < 4; j++) {
            size_t o = ((size_t)b * SSq + s0 + ty * 4 + i) * DDd + h * DKk + tx * 4 + j;
            out[o] = acc[i][j];
        }
}

// ---------------- residual + LayerNorm: out = LN(x + res) * g + b ----------------
__global__ void ln_kernel(const float* __restrict__ x, const float* __restrict__ res,
                          const float* __restrict__ g, const float* __restrict__ b,
                          float* __restrict__ out)
{
    int row = blockIdx.x;          // over B*S
    const float* xr = x + (size_t)row * DDd;
    const float* rr = res + (size_t)row * DDd;
    __shared__ float redA[33], redB[33];
    int tid = threadIdx.x;

    float loc[4];
    float s1 = 0.f, s2 = 0.f;
#pragma unroll
    for (int i = 0; i < 4; i++) {
        int d = tid + i * 256;
        float v = xr[d] + rr[d];
        loc[i] = v;
        s1 += v;
        s2 += v * v;
    }
#pragma unroll
    for (int o = 16; o; o >>= 1) {
        s1 += __shfl_xor_sync(0xffffffffu, s1, o);
        s2 += __shfl_xor_sync(0xffffffffu, s2, o);
    }
    if ((tid & 31) == 0) { redA[tid >> 5] = s1; redB[tid >> 5] = s2; }
    __syncthreads();
    if (tid < 32) {
        float a = (tid < 8) ? redA[tid] : 0.f;
        float c = (tid < 8) ? redB[tid] : 0.f;
#pragma unroll
        for (int o = 4; o; o >>= 1) {
            a += __shfl_xor_sync(0xffffffffu, a, o);
            c += __shfl_xor_sync(0xffffffffu, c, o);
        }
        if (tid == 0) { redA[32] = a; redB[32] = c; }
    }
    __syncthreads();
    float mu  = redA[32] * (1.f / DDd);
    float var = redB[32] * (1.f / DDd) - mu * mu;
    float rstd = rsqrtf(var + 1e-5f);
#pragma unroll
    for (int i = 0; i < 4; i++) {
        int d = tid + i * 256;
        out[(size_t)row * DDd + d] = (loc[i] - mu) * rstd * g[d] + b[d];
    }
}

// ---------------- host-side orchestration ----------------
extern "C" void kernel_launch(void* const* d_in, const int* in_sizes, int n_in,
                              void* d_out, int out_size)
{
    const float* x      = (const float*)d_in[0];
    const float* memory = (const float*)d_in[1];
    const float* Wq  = (const float*)d_in[2];
    const float* Wk  = (const float*)d_in[3];
    const float* Wv  = (const float*)d_in[4];
    const float* Wr  = (const float*)d_in[5];
    const float* Wo  = (const float*)d_in[6];
    const float* rwb = (const float*)d_in[7];
    const float* rrb = (const float*)d_in[8];
    const float* ln1g = (const float*)d_in[9];
    const float* ln1b = (const float*)d_in[10];
    const float* ln2g = (const float*)d_in[11];
    const float* ln2b = (const float*)d_in[12];
    const float* W1  = (const float*)d_in[13];
    const float* b1  = (const float*)d_in[14];
    const float* W2  = (const float*)d_in[15];
    const float* b2  = (const float*)d_in[16];
    float* out = (float*)d_out;

    float *pos, *kv, *q, *k, *v, *r, *sc, *rel, *attn, *tmp, *ff, *h, *h1;
    cudaGetSymbolAddress((void**)&pos,  g_pos);
    cudaGetSymbolAddress((void**)&kv,   g_kv);
    cudaGetSymbolAddress((void**)&q,    g_q);
    cudaGetSymbolAddress((void**)&k,    g_k);
    cudaGetSymbolAddress((void**)&v,    g_v);
    cudaGetSymbolAddress((void**)&r,    g_r);
    cudaGetSymbolAddress((void**)&sc,   g_sc);
    cudaGetSymbolAddress((void**)&rel,  g_rel);
    cudaGetSymbolAddress((void**)&attn, g_attn);
    cudaGetSymbolAddress((void**)&tmp,  g_tmp);
    cudaGetSymbolAddress((void**)&ff,   g_ff);
    cudaGetSymbolAddress((void**)&h,    g_h);
    cudaGetSymbolAddress((void**)&h1,   g_h1);

    const float scale = 0.125f;   // DK^-0.5

    pos_kernel<<<(TTt * DDd + 255) / 256, 256>>>(pos);

    const float* hcur = x;
    for (int l = 0; l < LL; l++) {
        concat_kernel<<<(BB * TTt * DDd + 255) / 256, 256>>>(
            kv, memory + (size_t)l * BB * MMm * DDd, hcur);

        dim3 gQ(DDd / 64, (BB * SSq) / 128);
        sgemm_kernel<<<gQ, 256>>>(hcur, Wq + (size_t)l * DDd * DDd, q,
                                  BB * SSq, DDd, DDd, scale, nullptr, 0);
        dim3 gKV(DDd / 64, (BB * TTt) / 128);
        sgemm_kernel<<<gKV, 256>>>(kv, Wk + (size_t)l * DDd * DDd, k,
                                   BB * TTt, DDd, DDd, 1.f, nullptr, 0);
        sgemm_kernel<<<gKV, 256>>>(kv, Wv + (size_t)l * DDd * DDd, v,
                                   BB * TTt, DDd, DDd, 1.f, nullptr, 0);
        dim3 gR(DDd / 64, TTt / 128);
        sgemm_kernel<<<gR, 256>>>(pos, Wr + (size_t)l * DDd * DDd, r,
                                  TTt, DDd, DDd, 1.f, nullptr, 0);

        dim3 gS(TTt / 64, SSq / 64, BB * HHh);
        scores_kernel<<<gS, 256>>>(q, rwb + l * HHh * DKk, k, 1, sc);
        scores_kernel<<<gS, 256>>>(q, rrb + l * HHh * DKk, r, 0, rel);

        softmax_kernel<<<BB * HHh * SSq, 256>>>(sc, rel);

        dim3 gA(SSq / 64, BB * HHh);
        attnv_kernel<<<gA, 256>>>(sc, v, attn);

        sgemm_kernel<<<gQ, 256>>>(attn, Wo + (size_t)l * DDd * DDd, tmp,
                                  BB * SSq, DDd, DDd, 1.f, nullptr, 0);
        ln_kernel<<<BB * SSq, 256>>>(tmp, hcur, ln1g + l * DDd, ln1b + l * DDd, h1);

        dim3 gF1(FFf / 64, (BB * SSq) / 128);
        sgemm_kernel<<<gF1, 256>>>(h1, W1 + (size_t)l * DDd * FFf, ff,
                                   BB * SSq, FFf, DDd, 1.f, b1 + l * FFf, 1);
        dim3 gF2(DDd / 64, (BB * SSq) / 128);
        sgemm_kernel<<<gF2, 256>>>(ff, W2 + (size_t)l * FFf * DDd, tmp,
                                   BB * SSq, DDd, FFf, 1.f, b2 + l * DDd, 0);

        float* hout = (l == LL - 1) ? out : h;
        ln_kernel<<<BB * SSq, 256>>>(tmp, h1, ln2g + l * DDd, ln2b + l * DDd, hout);
        hcur = h;
    }
}

// round 2
// speedup vs baseline: 3.0020x; 3.0020x over previous
#include <cuda_runtime.h>
#include <math.h>
#include <stdint.h>

// Problem dims
#define LL  4
#define BB  2
#define SSq 512
#define MMm 512
#define DDd 1024
#define HHh 16
#define DKk 64
#define FFf 4096
#define TTt (SSq + MMm)   // 1024

// ---------------- scratch (device globals; no allocation allowed) ----------------
__device__ float g_pos[TTt * DDd];
__device__ float g_kv [BB * TTt * DDd];
__device__ float g_q  [BB * SSq * DDd];
__device__ float g_k  [BB * TTt * DDd];
__device__ float g_v  [BB * TTt * DDd];
__device__ float g_r  [TTt * DDd];
__device__ float g_sc [(size_t)BB * HHh * SSq * TTt];
__device__ float g_rel[(size_t)BB * HHh * SSq * TTt];
__device__ float g_attn[BB * SSq * DDd];
__device__ float g_tmp [BB * SSq * DDd];
__device__ float g_ff  [BB * SSq * FFf];
__device__ float g_h   [BB * SSq * DDd];
__device__ float g_h1  [BB * SSq * DDd];

// ---------------- PTX helpers ----------------
__device__ __forceinline__ uint32_t f2tf32(float f) {
    uint32_t u;
    asm("cvt.rna.tf32.f32 %0, %1;" : "=r"(u) : "f"(f));
    return u;
}
__device__ __forceinline__ void mma_tf32(float c[4], const uint32_t a[4], const uint32_t b[2]) {
    asm volatile(
        "mma.sync.aligned.m16n8k8.row.col.f32.tf32.tf32.f32 "
        "{%0,%1,%2,%3},{%4,%5,%6,%7},{%8,%9},{%0,%1,%2,%3};"
        : "+f"(c[0]), "+f"(c[1]), "+f"(c[2]), "+f"(c[3])
        : "r"(a[0]), "r"(a[1]), "r"(a[2]), "r"(a[3]), "r"(b[0]), "r"(b[1]));
}
__device__ __forceinline__ void cp_async16(void* smem, const void* g) {
    uint32_t s = (uint32_t)__cvta_generic_to_shared(smem);
    asm volatile("cp.async.cg.shared.global [%0], [%1], 16;" :: "r"(s), "l"(g));
}
#define CP_COMMIT() asm volatile("cp.async.commit_group;")
#define CP_WAIT(n)  asm volatile("cp.async.wait_group %0;" :: "n"(n))

// ---------------- positional encodings ----------------
__global__ void pos_kernel(float* __restrict__ pos)
{
    int idx = blockIdx.x * blockDim.x + threadIdx.x;
    if (idx >= TTt * DDd) return;
    int t = idx / DDd, d = idx % DDd;
    int j = (d < DDd / 2) ? d : d - DDd / 2;
    double invf = exp(-((double)(2 * j) / (double)DDd) * log(10000.0));
    double ang  = (double)(TTt - 1 - t) * invf;
    pos[idx] = (d < DDd / 2) ? (float)sin(ang) : (float)cos(ang);
}

// ---------------- concat(memory[l], h) -> kv ----------------
__global__ void concat_kernel(float* __restrict__ kv, const float* __restrict__ mem,
                              const float* __restrict__ h)
{
    int idx = blockIdx.x * blockDim.x + threadIdx.x;
    if (idx >= BB * TTt * DDd) return;
    int d = idx % DDd;
    int t = (idx / DDd) % TTt;
    int b = idx / (DDd * TTt);
    kv[idx] = (t < MMm) ? mem[((size_t)b * MMm + t) * DDd + d]
                        : h[((size_t)b * SSq + (t - MMm)) * DDd + d];
}

// ======================================================================
// Tensor-core GEMM: C[M,N] = alpha*A[M,K]@B[K,N] (+bias)(+relu)
// BM=128 BN=128 BK=16, 256 threads (8 warps: 2m x 4n, warp tile 64x32)
// ======================================================================
__global__ void __launch_bounds__(256) tc_gemm(
    const float* __restrict__ A, const float* __restrict__ B, float* __restrict__ C,
    int M, int N, int K, float alpha, const float* __restrict__ bias, int relu)
{
    __shared__ __align__(16) float As[2][128][20];   // [m][k], pad 4
    __shared__ __align__(16) float Bs[2][16][136];   // [k][n], pad 8

    int tid = threadIdx.x, lane = tid & 31, warp = tid >> 5;
    int g = lane >> 2, tg = lane & 3;
    int wm = (warp & 1) * 64, wn = (warp >> 1) * 32;

    const float* Ag = A + (size_t)blockIdx.y * 128 * K;
    const float* Bg = B + blockIdx.x * 128;

    float acc[4][4][4];
#pragma unroll
    for (int mt = 0; mt < 4; mt++)
#pragma unroll
        for (int nt = 0; nt < 4; nt++)
#pragma unroll
            for (int i = 0; i < 4; i++) acc[mt][nt][i] = 0.f;

    int nk = K / 16;
    // prologue
    {
#pragma unroll
        for (int j = 0; j < 2; j++) {
            int chunk = tid + j * 256;
            int row = chunk >> 2, k0 = (chunk & 3) * 4;
            cp_async16(&As[0][row][k0], Ag + (size_t)row * K + k0);
        }
#pragma unroll
        for (int j = 0; j < 2; j++) {
            int chunk = tid + j * 256;
            int kk = chunk >> 5, n0 = (chunk & 31) * 4;
            cp_async16(&Bs[0][kk][n0], Bg + (size_t)kk * N + n0);
        }
        CP_COMMIT();
    }

    for (int kt = 0; kt < nk; kt++) {
        int buf = kt & 1;
        if (kt + 1 < nk) {
            int nb = buf ^ 1;
#pragma unroll
            for (int j = 0; j < 2; j++) {
                int chunk = tid + j * 256;
                int row = chunk >> 2, k0 = (chunk & 3) * 4;
                cp_async16(&As[nb][row][k0], Ag + (size_t)row * K + (kt + 1) * 16 + k0);
            }
#pragma unroll
            for (int j = 0; j < 2; j++) {
                int chunk = tid + j * 256;
                int kk = chunk >> 5, n0 = (chunk & 31) * 4;
                cp_async16(&Bs[nb][kk][n0], Bg + (size_t)((kt + 1) * 16 + kk) * N + n0);
            }
            CP_COMMIT();
            CP_WAIT(1);
        } else {
            CP_WAIT(0);
        }
        __syncthreads();

#pragma unroll
        for (int ks = 0; ks < 2; ks++) {
            uint32_t af[4][4], bf[4][2];
#pragma unroll
            for (int mt = 0; mt < 4; mt++) {
                int row = wm + mt * 16;
                af[mt][0] = f2tf32(As[buf][row + g][ks * 8 + tg]);
                af[mt][1] = f2tf32(As[buf][row + g + 8][ks * 8 + tg]);
                af[mt][2] = f2tf32(As[buf][row + g][ks * 8 + tg + 4]);
                af[mt][3] = f2tf32(As[buf][row + g + 8][ks * 8 + tg + 4]);
            }
#pragma unroll
            for (int nt = 0; nt < 4; nt++) {
                int col = wn + nt * 8 + g;
                bf[nt][0] = f2tf32(Bs[buf][ks * 8 + tg][col]);
                bf[nt][1] = f2tf32(Bs[buf][ks * 8 + tg + 4][col]);
            }
#pragma unroll
            for (int mt = 0; mt < 4; mt++)
#pragma unroll
                for (int nt = 0; nt < 4; nt++) mma_tf32(acc[mt][nt], af[mt], bf[nt]);
        }
        __syncthreads();
    }

    // epilogue
#pragma unroll
    for (int mt = 0; mt < 4; mt++) {
#pragma unroll
        for (int nt = 0; nt < 4; nt++) {
            int row = blockIdx.y * 128 + wm + mt * 16 + g;
            int col = blockIdx.x * 128 + wn + nt * 8 + tg * 2;
            float bx = 0.f, by = 0.f;
            if (bias) { bx = bias[col]; by = bias[col + 1]; }
            float v0 = acc[mt][nt][0] * alpha + bx;
            float v1 = acc[mt][nt][1] * alpha + by;
            float v2 = acc[mt][nt][2] * alpha + bx;
            float v3 = acc[mt][nt][3] * alpha + by;
            if (relu) {
                v0 = fmaxf(v0, 0.f); v1 = fmaxf(v1, 0.f);
                v2 = fmaxf(v2, 0.f); v3 = fmaxf(v3, 0.f);
            }
            *(float2*)(C + (size_t)row * N + col)       = make_float2(v0, v1);
            *(float2*)(C + (size_t)(row + 8) * N + col) = make_float2(v2, v3);
        }
    }
}

// ======================================================================
// Scores: out[z,s,t] = sum_dk (Q[b,s,h,dk]+bias[h,dk]) * KR[(b,)t,h,dk]
// 128x128 tile, K=64 in two 32-slabs, 8 warps (2m x 4n)
// ======================================================================
__global__ void __launch_bounds__(256) tc_scores(
    const float* __restrict__ Q, const float* __restrict__ qbias,
    const float* __restrict__ KR, int batched, float* __restrict__ out)
{
    __shared__ __align__(16) float Qs[128][36];  // [s][k], pad 4
    __shared__ __align__(16) float Ks[128][36];  // [t][k], pad 4

    int tid = threadIdx.x, lane = tid & 31, warp = tid >> 5;
    int g = lane >> 2, tg = lane & 3;
    int wm = (warp & 1) * 64, wn = (warp >> 1) * 32;

    int b = blockIdx.z / HHh, h = blockIdx.z % HHh;
    const float* qb = Q + (size_t)b * SSq * DDd + h * DKk;
    const float* kb = KR + (batched ? (size_t)b * TTt * DDd : 0) + h * DKk;
    const float* bias = qbias + h * DKk;
    int s0 = blockIdx.y * 128, t0 = blockIdx.x * 128;

    float acc[4][4][4];
#pragma unroll
    for (int mt = 0; mt < 4; mt++)
#pragma unroll
        for (int nt = 0; nt < 4; nt++)
#pragma unroll
            for (int i = 0; i < 4; i++) acc[mt][nt][i] = 0.f;

    for (int kt = 0; kt < 2; kt++) {
        int kbase = kt * 32;
        if (kt) __syncthreads();
#pragma unroll
        for (int j = 0; j < 4; j++) {
            int chunk = tid + j * 256;
            int row = chunk >> 3, k0 = (chunk & 7) * 4;
            float4 a = *(const float4*)(qb + (size_t)(s0 + row) * DDd + kbase + k0);
            float4 bb = *(const float4*)(bias + kbase + k0);
            Qs[row][k0 + 0] = a.x + bb.x;
            Qs[row][k0 + 1] = a.y + bb.y;
            Qs[row][k0 + 2] = a.z + bb.z;
            Qs[row][k0 + 3] = a.w + bb.w;
            float4 kv4 = *(const float4*)(kb + (size_t)(t0 + row) * DDd + kbase + k0);
            Ks[row][k0 + 0] = kv4.x;
            Ks[row][k0 + 1] = kv4.y;
            Ks[row][k0 + 2] = kv4.z;
            Ks[row][k0 + 3] = kv4.w;
        }
        __syncthreads();

#pragma unroll
        for (int ks = 0; ks < 4; ks++) {
            uint32_t af[4][4], bf[4][2];
#pragma unroll
            for (int mt = 0; mt < 4; mt++) {
                int row = wm + mt * 16;
                af[mt][0] = f2tf32(Qs[row + g][ks * 8 + tg]);
                af[mt][1] = f2tf32(Qs[row + g + 8][ks * 8 + tg]);
                af[mt][2] = f2tf32(Qs[row + g][ks * 8 + tg + 4]);
                af[mt][3] = f2tf32(Qs[row + g + 8][ks * 8 + tg + 4]);
            }
#pragma unroll
            for (int nt = 0; nt < 4; nt++) {
                int col = wn + nt * 8 + g;
                bf[nt][0] = f2tf32(Ks[col][ks * 8 + tg]);
                bf[nt][1] = f2tf32(Ks[col][ks * 8 + tg + 4]);
            }
#pragma unroll
            for (int mt = 0; mt < 4; mt++)
#pragma unroll
                for (int nt = 0; nt < 4; nt++) mma_tf32(acc[mt][nt], af[mt], bf[nt]);
        }
    }

#pragma unroll
    for (int mt = 0; mt < 4; mt++)
#pragma unroll
        for (int nt = 0; nt < 4; nt++) {
            int row = s0 + wm + mt * 16 + g;
            int col = t0 + wn + nt * 8 + tg * 2;
            size_t base = ((size_t)blockIdx.z * SSq + row) * TTt + col;
            *(float2*)(out + base)              = make_float2(acc[mt][nt][0], acc[mt][nt][1]);
            *(float2*)(out + base + 8 * TTt)    = make_float2(acc[mt][nt][2], acc[mt][nt][3]);
        }
}

// ======================================================================
// attn[b,s,h,dk] = sum_t W[z,s,t] * V[b,t,h,dk]
// BM=128, BN=64, BK=16, 8 warps (2m x 4n, warp tile 64x16)
// ======================================================================
__global__ void __launch_bounds__(256) tc_attnv(
    const float* __restrict__ W, const float* __restrict__ V, float* __restrict__ out)
{
    __shared__ __align__(16) float Ws[2][128][20];  // [s][t-chunk], pad 4
    __shared__ __align__(16) float Vs[2][16][72];   // [t][dk], pad 8

    int tid = threadIdx.x, lane = tid & 31, warp = tid >> 5;
    int g = lane >> 2, tg = lane & 3;
    int wm = (warp & 1) * 64, wn = (warp >> 1) * 16;

    int b = blockIdx.y / HHh, h = blockIdx.y % HHh;
    const float* wb = W + (size_t)blockIdx.y * SSq * TTt;
    const float* vb = V + (size_t)b * TTt * DDd + h * DKk;
    int s0 = blockIdx.x * 128;

    float acc[4][2][4];
#pragma unroll
    for (int mt = 0; mt < 4; mt++)
#pragma unroll
        for (int nt = 0; nt < 2; nt++)
#pragma unroll
            for (int i = 0; i < 4; i++) acc[mt][nt][i] = 0.f;

    const int nk = TTt / 16;   // 64
    {
#pragma unroll
        for (int j = 0; j < 2; j++) {
            int chunk = tid + j * 256;
            int row = chunk >> 2, k0 = (chunk & 3) * 4;
            cp_async16(&Ws[0][row][k0], wb + (size_t)(s0 + row) * TTt + k0);
        }
        {
            int kk = tid >> 4, n0 = (tid & 15) * 4;
            cp_async16(&Vs[0][kk][n0], vb + (size_t)kk * DDd + n0);
        }
        CP_COMMIT();
    }

    for (int kt = 0; kt < nk; kt++) {
        int buf = kt & 1;
        if (kt + 1 < nk) {
            int nb = buf ^ 1;
#pragma unroll
            for (int j = 0; j < 2; j++) {
                int chunk = tid + j * 256;
                int row = chunk >> 2, k0 = (chunk & 3) * 4;
                cp_async16(&Ws[nb][row][k0], wb + (size_t)(s0 + row) * TTt + (kt + 1) * 16 + k0);
            }
            {
                int kk = tid >> 4, n0 = (tid & 15) * 4;
                cp_async16(&Vs[nb][kk][n0], vb + (size_t)((kt + 1) * 16 + kk) * DDd + n0);
            }
            CP_COMMIT();
            CP_WAIT(1);
        } else {
            CP_WAIT(0);
        }
        __syncthreads();

#pragma unroll
        for (int ks = 0; ks < 2; ks++) {
            uint32_t af[4][4], bf[2][2];
#pragma unroll
            for (int mt = 0; mt < 4; mt++) {
                int row = wm + mt * 16;
                af[mt][0] = f2tf32(Ws[buf][row + g][ks * 8 + tg]);
                af[mt][1] = f2tf32(Ws[buf][row + g + 8][ks * 8 + tg]);
                af[mt][2] = f2tf32(Ws[buf][row + g][ks * 8 + tg + 4]);
                af[mt][3] = f2tf32(Ws[buf][row + g + 8][ks * 8 + tg + 4]);
            }
#pragma unroll
            for (int nt = 0; nt < 2; nt++) {
                int col = wn + nt * 8 + g;
                bf[nt][0] = f2tf32(Vs[buf][ks * 8 + tg][col]);
                bf[nt][1] = f2tf32(Vs[buf][ks * 8 + tg + 4][col]);
            }
#pragma unroll
            for (int mt = 0; mt < 4; mt++)
#pragma unroll
                for (int nt = 0; nt < 2; nt++) mma_tf32(acc[mt][nt], af[mt], bf[nt]);
        }
        __syncthreads();
    }

    float* op = out + (size_t)b * SSq * DDd + h * DKk;
#pragma unroll
    for (int mt = 0; mt < 4; mt++)
#pragma unroll
        for (int nt = 0; nt < 2; nt++) {
            int row = s0 + wm + mt * 16 + g;
            int col = wn + nt * 8 + tg * 2;
            *(float2*)(op + (size_t)row * DDd + col)       = make_float2(acc[mt][nt][0], acc[mt][nt][1]);
            *(float2*)(op + (size_t)(row + 8) * DDd + col) = make_float2(acc[mt][nt][2], acc[mt][nt][3]);
        }
}

// ---------------- shift + mask + softmax (in-place on sc) ----------------
__global__ void softmax_kernel(float* __restrict__ sc, const float* __restrict__ rel)
{
    int row = blockIdx.x;          // over B*H*S
    int s = row % SSq;
    float* lr = sc + (size_t)row * TTt;
    const float* rr = rel + (size_t)row * TTt;
    int valid = MMm + s + 1;

    __shared__ float vals[TTt];
    __shared__ float red[33];
    int tid = threadIdx.x;

    float lmax = -1e30f;
    for (int t = tid; t < TTt; t += 256) {
        float v = -1e30f;
        if (t < valid) v = lr[t] + rr[t - s + SSq - 1];
        vals[t] = v;
        lmax = fmaxf(lmax, v);
    }
#pragma unroll
    for (int o = 16; o; o >>= 1) lmax = fmaxf(lmax, __shfl_xor_sync(0xffffffffu, lmax, o));
    if ((tid & 31) == 0) red[tid >> 5] = lmax;
    __syncthreads();
    if (tid < 32) {
        float v2 = (tid < 8) ? red[tid] : -1e30f;
#pragma unroll
        for (int o = 4; o; o >>= 1) v2 = fmaxf(v2, __shfl_xor_sync(0xffffffffu, v2, o));
        if (tid == 0) red[32] = v2;
    }
    __syncthreads();
    float m = red[32];
    __syncthreads();

    float lsum = 0.f;
    for (int t = tid; t < TTt; t += 256) {
        float e = (t < valid) ? __expf(vals[t] - m) : 0.f;
        vals[t] = e;
        lsum += e;
    }
#pragma unroll
    for (int o = 16; o; o >>= 1) lsum += __shfl_xor_sync(0xffffffffu, lsum, o);
    if ((tid & 31) == 0) red[tid >> 5] = lsum;
    __syncthreads();
    if (tid < 32) {
        float v2 = (tid < 8) ? red[tid] : 0.f;
#pragma unroll
        for (int o = 4; o; o >>= 1) v2 += __shfl_xor_sync(0xffffffffu, v2, o);
        if (tid == 0) red[32] = v2;
    }
    __syncthreads();
    float inv = 1.f / red[32];
    for (int t = tid; t < TTt; t += 256) lr[t] = vals[t] * inv;
}

// ---------------- residual + LayerNorm ----------------
__global__ void ln_kernel(const float* __restrict__ x, const float* __restrict__ res,
                          const float* __restrict__ g, const float* __restrict__ b,
                          float* __restrict__ out)
{
    int row = blockIdx.x;          // over B*S
    const float* xr = x + (size_t)row * DDd;
    const float* rr = res + (size_t)row * DDd;
    __shared__ float redA[33], redB[33];
    int tid = threadIdx.x;

    float loc[4];
    float s1 = 0.f, s2 = 0.f;
#pragma unroll
    for (int i = 0; i < 4; i++) {
        int d = tid + i * 256;
        float v = xr[d] + rr[d];
        loc[i] = v;
        s1 += v;
        s2 += v * v;
    }
#pragma unroll
    for (int o = 16; o; o >>= 1) {
        s1 += __shfl_xor_sync(0xffffffffu, s1, o);
        s2 += __shfl_xor_sync(0xffffffffu, s2, o);
    }
    if ((tid & 31) == 0) { redA[tid >> 5] = s1; redB[tid >> 5] = s2; }
    __syncthreads();
    if (tid < 32) {
        float a = (tid < 8) ? redA[tid] : 0.f;
        float c = (tid < 8) ? redB[tid] : 0.f;
#pragma unroll
        for (int o = 4; o; o >>= 1) {
            a += __shfl_xor_sync(0xffffffffu, a, o);
            c += __shfl_xor_sync(0xffffffffu, c, o);
        }
        if (tid == 0) { redA[32] = a; redB[32] = c; }
    }
    __syncthreads();
    float mu  = redA[32] * (1.f / DDd);
    float var = redB[32] * (1.f / DDd) - mu * mu;
    float rstd = rsqrtf(var + 1e-5f);
#pragma unroll
    for (int i = 0; i < 4; i++) {
        int d = tid + i * 256;
        out[(size_t)row * DDd + d] = (loc[i] - mu) * rstd * g[d] + b[d];
    }
}

// ---------------- host-side orchestration ----------------
extern "C" void kernel_launch(void* const* d_in, const int* in_sizes, int n_in,
                              void* d_out, int out_size)
{
    const float* x      = (const float*)d_in[0];
    const float* memory = (const float*)d_in[1];
    const float* Wq  = (const float*)d_in[2];
    const float* Wk  = (const float*)d_in[3];
    const float* Wv  = (const float*)d_in[4];
    const float* Wr  = (const float*)d_in[5];
    const float* Wo  = (const float*)d_in[6];
    const float* rwb = (const float*)d_in[7];
    const float* rrb = (const float*)d_in[8];
    const float* ln1g = (const float*)d_in[9];
    const float* ln1b = (const float*)d_in[10];
    const float* ln2g = (const float*)d_in[11];
    const float* ln2b = (const float*)d_in[12];
    const float* W1  = (const float*)d_in[13];
    const float* b1  = (const float*)d_in[14];
    const float* W2  = (const float*)d_in[15];
    const float* b2  = (const float*)d_in[16];
    float* out = (float*)d_out;

    float *pos, *kv, *q, *k, *v, *r, *sc, *rel, *attn, *tmp, *ff, *h, *h1;
    cudaGetSymbolAddress((void**)&pos,  g_pos);
    cudaGetSymbolAddress((void**)&kv,   g_kv);
    cudaGetSymbolAddress((void**)&q,    g_q);
    cudaGetSymbolAddress((void**)&k,    g_k);
    cudaGetSymbolAddress((void**)&v,    g_v);
    cudaGetSymbolAddress((void**)&r,    g_r);
    cudaGetSymbolAddress((void**)&sc,   g_sc);
    cudaGetSymbolAddress((void**)&rel,  g_rel);
    cudaGetSymbolAddress((void**)&attn, g_attn);
    cudaGetSymbolAddress((void**)&tmp,  g_tmp);
    cudaGetSymbolAddress((void**)&ff,   g_ff);
    cudaGetSymbolAddress((void**)&h,    g_h);
    cudaGetSymbolAddress((void**)&h1,   g_h1);

    const float scale = 0.125f;   // DK^-0.5

    pos_kernel<<<(TTt * DDd + 255) / 256, 256>>>(pos);

    const float* hcur = x;
    for (int l = 0; l < LL; l++) {
        concat_kernel<<<(BB * TTt * DDd + 255) / 256, 256>>>(
            kv, memory + (size_t)l * BB * MMm * DDd, hcur);

        dim3 gQ(DDd / 128, (BB * SSq) / 128);
        tc_gemm<<<gQ, 256>>>(hcur, Wq + (size_t)l * DDd * DDd, q,
                             BB * SSq, DDd, DDd, scale, nullptr, 0);
        dim3 gKV(DDd / 128, (BB * TTt) / 128);
        tc_gemm<<<gKV, 256>>>(kv, Wk + (size_t)l * DDd * DDd, k,
                              BB * TTt, DDd, DDd, 1.f, nullptr, 0);
        tc_gemm<<<gKV, 256>>>(kv, Wv + (size_t)l * DDd * DDd, v,
                              BB * TTt, DDd, DDd, 1.f, nullptr, 0);
        dim3 gR(DDd / 128, TTt / 128);
        tc_gemm<<<gR, 256>>>(pos, Wr + (size_t)l * DDd * DDd, r,
                             TTt, DDd, DDd, 1.f, nullptr, 0);

        dim3 gS(TTt / 128, SSq / 128, BB * HHh);
        tc_scores<<<gS, 256>>>(q, rwb + l * HHh * DKk, k, 1, sc);
        tc_scores<<<gS, 256>>>(q, rrb + l * HHh * DKk, r, 0, rel);

        softmax_kernel<<<BB * HHh * SSq, 256>>>(sc, rel);

        dim3 gA(SSq / 128, BB * HHh);
        tc_attnv<<<gA, 256>>>(sc, v, attn);

        tc_gemm<<<gQ, 256>>>(attn, Wo + (size_t)l * DDd * DDd, tmp,
                             BB * SSq, DDd, DDd, 1.f, nullptr, 0);
        ln_kernel<<<BB * SSq, 256>>>(tmp, hcur, ln1g + l * DDd, ln1b + l * DDd, h1);

        dim3 gF1(FFf / 128, (BB * SSq) / 128);
        tc_gemm<<<gF1, 256>>>(h1, W1 + (size_t)l * DDd * FFf, ff,
                              BB * SSq, FFf, DDd, 1.f, b1 + l * FFf, 1);
        dim3 gF2(DDd / 128, (BB * SSq) / 128);
        tc_gemm<<<gF2, 256>>>(ff, W2 + (size_t)l * FFf * DDd, tmp,
                              BB * SSq, DDd, FFf, 1.f, b2 + l * DDd, 0);

        float* hout = (l == LL - 1) ? out : h;
        ln_kernel<<<BB * SSq, 256>>>(tmp, h1, ln2g + l * DDd, ln2b + l * DDd, hout);
        hcur = h;
    }
}